// round 10
// baseline (speedup 1.0000x reference)
#include <cuda_runtime.h>
#include <cstdint>

// Problem constants (fixed by the reference's setup_inputs)
#define CC      256
#define HH      1024
#define WW      1024
#define STRIDE  153
#define GRIDSZ  76
#define OHOFF   50
#define OWOFF   50
#define NCH     7
#define NCW     7

#define COLS4   (WW / 4)          // 256 float4 columns per row
#define ROWS_PER_BLOCK 8

// Decoded 7x7 cell_erase table + per-(cellrow, float4-column) 4-bit lane masks.
// Scratch lives in __device__ globals (no allocation allowed).
__device__ unsigned char g_cell[NCH * NCW];
__device__ unsigned char g_colmask[NCH * COLS4];   // nibble per (cix, col)

// cell_erase arrives with an ambiguous dtype (jax bool). Sniff the encoding:
//  - 12 leading int32 reads all in {0,1}      -> int32 encoding
//  - else all in {0.0f,1.0f} as float         -> float32 encoding
//  - else                                     -> 1-byte bool encoding
// For ~49 Bernoulli(0.5) cells misclassification probability is ~(2/16)^12.
// Then build g_colmask: for each cell-row index cix and float4 column col,
// the 4-bit lane mask  OR_k( in_w(w0+k) & cell[cix][cj(w0+k)] ).
__global__ void decode_cell_kernel(const void* __restrict__ cell_raw) {
    __shared__ unsigned char s_cell[NCH * NCW];
    if (threadIdx.x == 0) {
        const int32_t* ci = (const int32_t*)cell_raw;
        const float*   cf = (const float*)cell_raw;
        const unsigned char* cb = (const unsigned char*)cell_raw;
        bool is_i32 = true;
        for (int i = 0; i < 12; i++) {
            int v = ci[i];
            if (v != 0 && v != 1) { is_i32 = false; break; }
        }
        bool is_f32 = false;
        if (!is_i32) {
            is_f32 = true;
            for (int i = 0; i < 12; i++) {
                float v = cf[i];
                if (v != 0.0f && v != 1.0f) { is_f32 = false; break; }
            }
        }
        for (int i = 0; i < NCH * NCW; i++) {
            unsigned char m;
            if (is_i32)      m = (unsigned char)(ci[i] != 0);
            else if (is_f32) m = (unsigned char)(cf[i] != 0.0f);
            else             m = (unsigned char)(cb[i] != 0);
            s_cell[i] = m;
            g_cell[i] = m;
        }
    }
    __syncthreads();

    int col = threadIdx.x;          // 0..255
    if (col < COLS4) {
        #pragma unroll
        for (int cix = 0; cix < NCH; cix++) {
            unsigned m = 0;
            #pragma unroll
            for (int k = 0; k < 4; k++) {
                int rj = col * 4 + k - OWOFF;
                if (rj >= 0 && (rj % STRIDE) < GRIDSZ) {
                    int cj = rj / STRIDE;                  // <= 6, clamp no-op
                    if (cj > NCW - 1) cj = NCW - 1;
                    if (s_cell[cix * NCW + cj]) m |= (1u << k);
                }
            }
            g_colmask[cix * COLS4 + col] = (unsigned char)m;
        }
    }
}

// Elementwise masked select. Each block owns 8 consecutive rows of one
// channel (8 | 1024, so a block never straddles a channel); each thread owns
// one float4 column in all 8 rows. All (up to 16) loads are issued as
// predicated LDG.128s up front (MLP_p1 ~16): x is skipped where the line is
// fully masked, noise where fully unmasked. Streaming cache ops avoid L2
// retention on a touch-once ~3 GB stream. Occupancy drops (~25%) from the
// register footprint, but in-flight bytes per SM (>100 KB) far exceed the
// ~15 KB needed to cover DRAM latency at this BW — MLP, not occupancy, is
// the binding resource here.
__global__ void __launch_bounds__(256)
grid_erase_kernel(const float4* __restrict__ x,
                  const float4* __restrict__ noise,
                  float4* __restrict__ out) {
    const int col  = threadIdx.x;                 // 0..255
    const int row0 = blockIdx.x * ROWS_PER_BLOCK; // global row (c*1024 + h)
    const int h0   = row0 & (HH - 1);

    unsigned mrow[ROWS_PER_BLOCK];
    #pragma unroll
    for (int r = 0; r < ROWS_PER_BLOCK; r++) {
        int ri = h0 + r - OHOFF;
        unsigned m = 0;
        if (ri >= 0 && (ri % STRIDE) < GRIDSZ) {
            int cix = ri / STRIDE;                // <= 6 for ri <= 973
            m = (unsigned)__ldg(&g_colmask[cix * COLS4 + col]);
        }
        mrow[r] = m;
    }

    const size_t base = (size_t)row0 * COLS4 + col;

    float4 xv[ROWS_PER_BLOCK], nv[ROWS_PER_BLOCK];
    #pragma unroll
    for (int r = 0; r < ROWS_PER_BLOCK; r++) {
        size_t i = base + (size_t)r * COLS4;
        if (mrow[r] != 0xFu) xv[r] = __ldcs(x + i);      // any lane keeps x
        if (mrow[r] != 0u)   nv[r] = __ldcs(noise + i);  // any lane erased
    }

    #pragma unroll
    for (int r = 0; r < ROWS_PER_BLOCK; r++) {
        unsigned m = mrow[r];
        float4 o;
        o.x = (m & 1u) ? nv[r].x : xv[r].x;
        o.y = (m & 2u) ? nv[r].y : xv[r].y;
        o.z = (m & 4u) ? nv[r].z : xv[r].z;
        o.w = (m & 8u) ? nv[r].w : xv[r].w;
        __stcs(out + base + (size_t)r * COLS4, o);
    }
}

extern "C" void kernel_launch(void* const* d_in, const int* in_sizes, int n_in,
                              void* d_out, int out_size) {
    const float4* x     = (const float4*)d_in[0];
    const float4* noise = (const float4*)d_in[1];
    const void*   cell  = d_in[2];
    float4*       out   = (float4*)d_out;

    decode_cell_kernel<<<1, 256>>>(cell);

    const unsigned int nrows  = (unsigned int)CC * HH;         // 262144
    const unsigned int blocks = nrows / ROWS_PER_BLOCK;        // 32768
    grid_erase_kernel<<<blocks, 256>>>(x, noise, out);
}

// round 15
// speedup vs baseline: 1.0003x; 1.0003x over previous
#include <cuda_runtime.h>
#include <cstdint>

// Problem constants (fixed by the reference's setup_inputs)
#define CC      256
#define HH      1024
#define WW      1024
#define STRIDE  153
#define GRIDSZ  76
#define OHOFF   50
#define OWOFF   50
#define NCH     7
#define NCW     7

#define COLS4   (WW / 4)          // 256 float4 columns per row
#define ROWS_PER_BLOCK 4          // best measured config (R6): MLP_p1~8

// Decoded 7x7 cell_erase table + per-(cellrow, float4-column) 4-bit lane masks.
// Scratch lives in __device__ globals (no allocation allowed).
__device__ unsigned char g_cell[NCH * NCW];
__device__ unsigned char g_colmask[NCH * COLS4];   // nibble per (cix, col)

// cell_erase arrives with an ambiguous dtype (jax bool). Sniff the encoding:
//  - 12 leading int32 reads all in {0,1}      -> int32 encoding
//  - else all in {0.0f,1.0f} as float         -> float32 encoding
//  - else                                     -> 1-byte bool encoding
// For ~49 Bernoulli(0.5) cells misclassification probability is ~(2/16)^12.
// Then build g_colmask: for each cell-row index cix and float4 column col,
// the 4-bit lane mask  OR_k( in_w(w0+k) & cell[cix][cj(w0+k)] ).
__global__ void decode_cell_kernel(const void* __restrict__ cell_raw) {
    __shared__ unsigned char s_cell[NCH * NCW];
    if (threadIdx.x == 0) {
        const int32_t* ci = (const int32_t*)cell_raw;
        const float*   cf = (const float*)cell_raw;
        const unsigned char* cb = (const unsigned char*)cell_raw;
        bool is_i32 = true;
        for (int i = 0; i < 12; i++) {
            int v = ci[i];
            if (v != 0 && v != 1) { is_i32 = false; break; }
        }
        bool is_f32 = false;
        if (!is_i32) {
            is_f32 = true;
            for (int i = 0; i < 12; i++) {
                float v = cf[i];
                if (v != 0.0f && v != 1.0f) { is_f32 = false; break; }
            }
        }
        for (int i = 0; i < NCH * NCW; i++) {
            unsigned char m;
            if (is_i32)      m = (unsigned char)(ci[i] != 0);
            else if (is_f32) m = (unsigned char)(cf[i] != 0.0f);
            else             m = (unsigned char)(cb[i] != 0);
            s_cell[i] = m;
            g_cell[i] = m;
        }
    }
    __syncthreads();

    int col = threadIdx.x;          // 0..255
    if (col < COLS4) {
        #pragma unroll
        for (int cix = 0; cix < NCH; cix++) {
            unsigned m = 0;
            #pragma unroll
            for (int k = 0; k < 4; k++) {
                int rj = col * 4 + k - OWOFF;
                if (rj >= 0 && (rj % STRIDE) < GRIDSZ) {
                    int cj = rj / STRIDE;                  // <= 6, clamp no-op
                    if (cj > NCW - 1) cj = NCW - 1;
                    if (s_cell[cix * NCW + cj]) m |= (1u << k);
                }
            }
            g_colmask[cix * COLS4 + col] = (unsigned char)m;
        }
    }
}

// Elementwise masked select. Each block owns 4 consecutive rows of one
// channel (4 | 1024, never straddles a channel); each thread owns one float4
// column in all 4 rows. All (up to 8) loads issue as predicated LDG.128s up
// front (MLP_p1 ~8 — the measured sweet spot; 16 regressed via occupancy).
// x is skipped where the line is fully masked, noise where fully unmasked.
// Streaming cache ops avoid L2 retention on a touch-once ~3 GB stream.
// ALL indexing is 32-bit: total float4 count is 2^26 < 2^31, so uint offsets
// are exact; this removes the 64-bit address IMAD chains that inflated the
// register count (45) and capped occupancy at 48%.
__global__ void __launch_bounds__(256)
grid_erase_kernel(const float4* __restrict__ x,
                  const float4* __restrict__ noise,
                  float4* __restrict__ out) {
    const unsigned col  = threadIdx.x;                 // 0..255
    const unsigned row0 = blockIdx.x * ROWS_PER_BLOCK; // global row (c*1024+h)
    const unsigned h0   = row0 & (HH - 1);

    unsigned mrow[ROWS_PER_BLOCK];
    #pragma unroll
    for (int r = 0; r < ROWS_PER_BLOCK; r++) {
        int ri = (int)h0 + r - OHOFF;
        unsigned m = 0;
        if (ri >= 0 && (ri % STRIDE) < GRIDSZ) {
            int cix = ri / STRIDE;                // <= 6 for ri <= 973
            m = (unsigned)__ldg(&g_colmask[cix * COLS4 + col]);
        }
        mrow[r] = m;
    }

    const unsigned base = row0 * COLS4 + col;     // fits in 32 bits (max 2^26)

    float4 xv[ROWS_PER_BLOCK], nv[ROWS_PER_BLOCK];
    #pragma unroll
    for (int r = 0; r < ROWS_PER_BLOCK; r++) {
        unsigned i = base + (unsigned)r * COLS4;
        if (mrow[r] != 0xFu) xv[r] = __ldcs(x + i);      // any lane keeps x
        if (mrow[r] != 0u)   nv[r] = __ldcs(noise + i);  // any lane erased
    }

    #pragma unroll
    for (int r = 0; r < ROWS_PER_BLOCK; r++) {
        unsigned m = mrow[r];
        float4 o;
        o.x = (m & 1u) ? nv[r].x : xv[r].x;
        o.y = (m & 2u) ? nv[r].y : xv[r].y;
        o.z = (m & 4u) ? nv[r].z : xv[r].z;
        o.w = (m & 8u) ? nv[r].w : xv[r].w;
        __stcs(out + base + (unsigned)r * COLS4, o);
    }
}

extern "C" void kernel_launch(void* const* d_in, const int* in_sizes, int n_in,
                              void* d_out, int out_size) {
    const float4* x     = (const float4*)d_in[0];
    const float4* noise = (const float4*)d_in[1];
    const void*   cell  = d_in[2];
    float4*       out   = (float4*)d_out;

    decode_cell_kernel<<<1, 256>>>(cell);

    const unsigned int nrows  = (unsigned int)CC * HH;         // 262144
    const unsigned int blocks = nrows / ROWS_PER_BLOCK;        // 65536
    grid_erase_kernel<<<blocks, 256>>>(x, noise, out);
}

// round 16
// speedup vs baseline: 1.0120x; 1.0117x over previous
#include <cuda_runtime.h>
#include <cstdint>

// Problem constants (fixed by the reference's setup_inputs)
#define CC      256
#define HH      1024
#define WW      1024
#define STRIDE  153
#define GRIDSZ  76
#define OHOFF   50
#define OWOFF   50
#define NCH     7
#define NCW     7

#define COLS4   (WW / 4)          // 256 float4 columns per row
#define ROWS_PER_BLOCK 4          // measured sweet spot (MLP_p1~8)

// Single fused kernel: no decode pre-pass. Each thread derives its own lane
// mask directly from cell_erase:
//   - dtype sniff (jax bool may arrive as int32/float32/bool bytes): 12
//     broadcast loads, uniform branches. Misclassification probability for
//     ~49 Bernoulli(0.5) cells is ~(2/16)^12.
//   - the thread's 4 consecutive columns span at most TWO grid cells
//     (cell width 153 >= 4), so pack cell[cix][cj0] and cell[cix][cj1] for
//     all 7 cix into two 7-bit registers once; per-row mask is then ~6 ALU
//     ops with zero loads.
// Main data path unchanged from the best measured config: 4 rows/thread,
// predicated LDG.128 front-batch (skip x when line fully masked, skip noise
// when fully unmasked), streaming cache ops on a touch-once ~3 GB stream.
__global__ void __launch_bounds__(256)
grid_erase_kernel(const float4* __restrict__ x,
                  const float4* __restrict__ noise,
                  const void*  __restrict__ cell_raw,
                  float4* __restrict__ out) {
    const unsigned col  = threadIdx.x;                 // 0..255
    const unsigned row0 = blockIdx.x * ROWS_PER_BLOCK; // global row (c*1024+h)
    const unsigned h0   = row0 & (HH - 1);

    // ---- dtype sniff (uniform; all loads broadcast, L2-resident) ----
    const int32_t*       ci = (const int32_t*)cell_raw;
    const float*         cf = (const float*)cell_raw;
    const unsigned char* cb = (const unsigned char*)cell_raw;
    bool is_i32 = true;
    #pragma unroll
    for (int i = 0; i < 12; i++) {
        int v = __ldg(ci + i);
        is_i32 = is_i32 && (v == 0 || v == 1);
    }
    bool is_f32 = false;
    if (!is_i32) {
        is_f32 = true;
        #pragma unroll
        for (int i = 0; i < 12; i++) {
            float v = __ldg(cf + i);
            is_f32 = is_f32 && (v == 0.0f || v == 1.0f);
        }
    }

    // ---- per-thread column structure (computed once) ----
    // Lanes k=0..3 cover columns col*4+k. in_w lane bits split by which grid
    // cell column (cj) they fall in: at most two distinct cj per thread.
    unsigned inw_m0 = 0, inw_m1 = 0;
    int cj0 = -1, cj1 = -1;
    #pragma unroll
    for (int k = 0; k < 4; k++) {
        int rj = (int)col * 4 + k - OWOFF;
        if (rj >= 0 && (rj % STRIDE) < GRIDSZ) {
            int cj = rj / STRIDE;                 // <= 6 for rj <= 973
            if (cj > NCW - 1) cj = NCW - 1;
            if (cj0 < 0 || cj == cj0) { cj0 = cj; inw_m0 |= (1u << k); }
            else                      { cj1 = cj; inw_m1 |= (1u << k); }
        }
    }

    // Pack cell[cix][cj0] / cell[cix][cj1] over all 7 cix into bit registers.
    unsigned colbits0 = 0, colbits1 = 0;
    if (cj0 >= 0) {
        #pragma unroll
        for (int cix = 0; cix < NCH; cix++) {
            int idx = cix * NCW + cj0;
            bool v = is_i32 ? (__ldg(ci + idx) != 0)
                   : is_f32 ? (__ldg(cf + idx) != 0.0f)
                            : (__ldg(cb + idx) != 0);
            colbits0 |= (unsigned)v << cix;
        }
    }
    if (cj1 >= 0) {
        #pragma unroll
        for (int cix = 0; cix < NCH; cix++) {
            int idx = cix * NCW + cj1;
            bool v = is_i32 ? (__ldg(ci + idx) != 0)
                   : is_f32 ? (__ldg(cf + idx) != 0.0f)
                            : (__ldg(cb + idx) != 0);
            colbits1 |= (unsigned)v << cix;
        }
    }

    // ---- per-row masks (pure ALU) ----
    unsigned mrow[ROWS_PER_BLOCK];
    #pragma unroll
    for (int r = 0; r < ROWS_PER_BLOCK; r++) {
        int ri = (int)h0 + r - OHOFF;
        unsigned m = 0;
        if (ri >= 0 && (ri % STRIDE) < GRIDSZ) {
            int cix = ri / STRIDE;                // <= 6 for ri <= 973
            if (cix > NCH - 1) cix = NCH - 1;
            if ((colbits0 >> cix) & 1u) m |= inw_m0;
            if ((colbits1 >> cix) & 1u) m |= inw_m1;
        }
        mrow[r] = m;
    }

    // ---- main data path (unchanged from best config) ----
    const unsigned base = row0 * COLS4 + col;     // fits in 32 bits (max 2^26)

    float4 xv[ROWS_PER_BLOCK], nv[ROWS_PER_BLOCK];
    #pragma unroll
    for (int r = 0; r < ROWS_PER_BLOCK; r++) {
        unsigned i = base + (unsigned)r * COLS4;
        if (mrow[r] != 0xFu) xv[r] = __ldcs(x + i);      // any lane keeps x
        if (mrow[r] != 0u)   nv[r] = __ldcs(noise + i);  // any lane erased
    }

    #pragma unroll
    for (int r = 0; r < ROWS_PER_BLOCK; r++) {
        unsigned m = mrow[r];
        float4 o;
        o.x = (m & 1u) ? nv[r].x : xv[r].x;
        o.y = (m & 2u) ? nv[r].y : xv[r].y;
        o.z = (m & 4u) ? nv[r].z : xv[r].z;
        o.w = (m & 8u) ? nv[r].w : xv[r].w;
        __stcs(out + base + (unsigned)r * COLS4, o);
    }
}

extern "C" void kernel_launch(void* const* d_in, const int* in_sizes, int n_in,
                              void* d_out, int out_size) {
    const float4* x     = (const float4*)d_in[0];
    const float4* noise = (const float4*)d_in[1];
    const void*   cell  = d_in[2];
    float4*       out   = (float4*)d_out;

    const unsigned int nrows  = (unsigned int)CC * HH;         // 262144
    const unsigned int blocks = nrows / ROWS_PER_BLOCK;        // 65536
    grid_erase_kernel<<<blocks, 256>>>(x, noise, cell, out);
}